// round 12
// baseline (speedup 1.0000x reference)
#include <cuda_runtime.h>
#include <cuda_fp16.h>

// PLE layers, round 12: fp16 HMMA + ldmatrix + 2 CTAs/SM.
//   Latency-bound diagnosis: 4x fewer smem instructions via ldmatrix.x4
//   (A from half2 X, B from [n][k] W chunks, stride-20 anti-conflict pad),
//   fragment double-buffering restored, and 16 warps/SM via
//   __launch_bounds__(256,2): out_a/out_b fold per-expert through gmem RMW
//   (CTA-exclusive rows, L2-resident), only out_s register-resident.

#define BT      16384
#define IN_D    256
#define EXP_D   128
#define NE      8
#define TB      64
#define NTH     256
#define XSSF    260         // phase-1 fp32 X stride (words)
#define XS2     132         // phase-2 half2 X stride (uints); 132%32=4 -> LDSM conflict-free
#define WSN     20          // W chunk row stride (uints), [n][kp]; 20%32 -> 8 rows distinct banks
#define GSS     57
#define NBUF    4
#define CH_SM_U (128*WSN)   // 2560 uints per W smem slot (10240 B)
#define NCH     64          // chunks per stack

// smem word offsets (phase1 fp32 X unions with phase2 halfX+ring)
#define OFF_XS   0
#define OFF_WS   (TB*XS2)                    // 8448
#define OFF_WSM  18688                       // max(64*260, 8448+4*2560)
#define OFF_BSM  (OFF_WSM + TB*GSS)          // +3648
#define SMEM_WORDS (OFF_BSM + 3*1024)        // 25408 words = 101632 B

__device__ unsigned Wc2[3 * NE * NCH / 8 * 128 * 16 * 8];   // [sg][e][c][n][kp] fp16x2

__device__ __forceinline__ void cp16(void* smem_dst, const void* gsrc) {
    unsigned d = (unsigned)__cvta_generic_to_shared(smem_dst);
    asm volatile("cp.async.cg.shared.global [%0], [%1], 16;\n" :: "r"(d), "l"(gsrc));
}
__device__ __forceinline__ void cp_commit() { asm volatile("cp.async.commit_group;\n"); }
template<int N> __device__ __forceinline__ void cp_wait() {
    asm volatile("cp.async.wait_group %0;\n" :: "n"(N));
}

#define LDSM4(r0, r1, r2, r3, addr) \
    asm volatile("ldmatrix.sync.aligned.m8n8.x4.shared.b16 {%0,%1,%2,%3}, [%4];" \
                 : "=r"(r0), "=r"(r1), "=r"(r2), "=r"(r3) : "r"(addr))

__device__ __forceinline__ void mma16(float& c0, float& c1, float& c2, float& c3,
                                      unsigned a0, unsigned a1, unsigned a2, unsigned a3,
                                      unsigned b0, unsigned b1) {
    asm volatile(
        "mma.sync.aligned.m16n8k16.row.col.f32.f16.f16.f32 "
        "{%0,%1,%2,%3}, {%4,%5,%6,%7}, {%8,%9}, {%0,%1,%2,%3};\n"
        : "+f"(c0), "+f"(c1), "+f"(c2), "+f"(c3)
        : "r"(a0), "r"(a1), "r"(a2), "r"(a3), "r"(b0), "r"(b1));
}

// ---------------- prepass: W[e][k][n] -> [sg][e][c][n][kp] fp16x2 k-pairs ----------------
__global__ void w_convert2(const float* __restrict__ Wa, const float* __restrict__ Wb,
                           const float* __restrict__ Wsx) {
    int id = blockIdx.x * blockDim.x + threadIdx.x;   // 393216 threads
    int kp = id & 15;
    int n  = (id >> 4) & 127;
    int c  = (id >> 11) & 7;
    int e  = (id >> 14) & 7;
    int sg = id >> 17;
    const float* W = (sg == 0) ? Wa : (sg == 1) ? Wb : Wsx;
    int k = c * 32 + 2 * kp;
    const float* p = W + ((size_t)e * IN_D + k) * EXP_D + n;
    __half2 h = __floats2half2_rn(p[0], p[EXP_D]);    // low = even k
    Wc2[id] = *(unsigned*)&h;
}

// ---------------- main fused kernel ----------------
__global__ __launch_bounds__(NTH, 2)
void ple_kernel(const float* __restrict__ xa, const float* __restrict__ xb,
                const float* __restrict__ xsh,
                const float* __restrict__ ba, const float* __restrict__ bb,
                const float* __restrict__ bsx,
                const float* __restrict__ Ga, const float* __restrict__ Gb,
                const float* __restrict__ Gq,
                float* __restrict__ out)
{
    extern __shared__ float smem[];
    float*    xsf = smem + OFF_XS;                  // phase 1: fp32 X tile
    unsigned* xs2 = (unsigned*)(smem + OFF_XS);     // phase 2: half2 X tile
    unsigned* wsu = (unsigned*)(smem + OFF_WS);     // phase 2: W ring
    float*    wsm = smem + OFF_WSM;
    float*    bsm = smem + OFF_BSM;

    const int tid  = threadIdx.x;
    const int lane = tid & 31;
    const int wid  = tid >> 5;
    const int gid  = lane >> 2;
    const int tig  = lane & 3;
    const int wm   = wid >> 2;                // 0..1
    const int wn   = wid & 3;                 // 0..3
    const int sub  = lane >> 3;               // ldmatrix quadrant
    const int l7   = lane & 7;
    const int row0 = blockIdx.x * TB;
    const size_t OS = (size_t)BT * EXP_D;

    const unsigned xs2_u = (unsigned)__cvta_generic_to_shared(xs2);
    const unsigned wsu_u = (unsigned)__cvta_generic_to_shared(wsu);

    // ldmatrix lane base addresses (bytes)
    unsigned addrA[2], addrB[2];
    #pragma unroll
    for (int mt = 0; mt < 2; ++mt) {
        int rowA = wm * 32 + mt * 16 + (sub & 1) * 8 + l7;
        int colp = (sub >> 1) * 4;                       // uints
        addrA[mt] = xs2_u + (rowA * XS2 + colp) * 4;
    }
    #pragma unroll
    for (int ntp = 0; ntp < 2; ++ntp) {
        int rowB = wn * 32 + ntp * 16 + (sub >> 1) * 8 + l7;
        int colp = (sub & 1) * 4;                        // uints
        addrB[ntp] = wsu_u + (rowB * WSN + colp) * 4;
    }

    for (int i = tid; i < 1024; i += NTH) {
        bsm[i]        = __ldg(ba + i);
        bsm[1024 + i] = __ldg(bb + i);
        bsm[2048 + i] = __ldg(bsx + i);
    }

    // ---------------- Phase 1: gate logits + softmax on RAW fp32 X ----------------
    #pragma unroll 1
    for (int sg = 0; sg < 3; ++sg) {
        const float* X = (sg == 0) ? xa : (sg == 1) ? xb : xsh;
        const float* G = (sg == 0) ? Ga : (sg == 1) ? Gb : Gq;
        const int NG   = (sg == 2) ? 24 : 16;
        const int WOFF = sg * 16;

        __syncthreads();
        {
            const float4* src = (const float4*)(X + (size_t)row0 * IN_D);
            #pragma unroll
            for (int j = 0; j < 16; ++j) {
                int idx = tid + j * NTH;
                int r = idx >> 6, s4 = (idx & 63) << 2;
                cp16(xsf + r * XSSF + s4, src + idx);
            }
            cp_commit();
        }
        cp_wait<0>();
        __syncthreads();

        for (int idx = tid; idx < TB * NG; idx += NTH) {
            int r = idx / NG, g = idx - r * NG;
            const float4* xp = (const float4*)(xsf + r * XSSF);
            const float4* gp = (const float4*)(G + (size_t)g * IN_D);
            float acc = 0.f;
            #pragma unroll 8
            for (int k = 0; k < IN_D / 4; ++k) {
                float4 xv = xp[k];
                float4 gv = __ldg(gp + k);
                acc += xv.x * gv.x; acc += xv.y * gv.y;
                acc += xv.z * gv.z; acc += xv.w * gv.w;
            }
            wsm[r * GSS + WOFF + g] = acc;
        }
        __syncthreads();

        if (tid < TB) {
            float* wr = wsm + tid * GSS + WOFF;
            float m = wr[0];
            for (int g = 1; g < NG; ++g) m = fmaxf(m, wr[g]);
            float s = 0.f;
            for (int g = 0; g < NG; ++g) { float e = expf(wr[g] - m); wr[g] = e; s += e; }
            float inv = 1.f / s;
            for (int g = 0; g < NG; ++g) wr[g] *= inv;
        }
    }

    // ---------------- Phase 2: fp16 expert GEMMs (ldmatrix) + gated folds ----------------
    float os[2][4][4] = {};     // out_s register accumulators
    float ec[2][4][4];

    #pragma unroll 1
    for (int sg = 0; sg < 3; ++sg) {
        const float* X = (sg == 0) ? xa : (sg == 1) ? xb : xsh;
        const unsigned* Wg = Wc2 + (size_t)sg * (NE * 8 * 128 * 16);

        __syncthreads();      // prior xs/ws readers done
        {   // stage X as half2 (LDG -> cvt -> STS)
            const float4* src = (const float4*)(X + (size_t)row0 * IN_D);
            #pragma unroll
            for (int j = 0; j < 16; ++j) {
                int idx = tid + j * NTH;
                int r = idx >> 6, k4 = idx & 63;
                float4 v = __ldg(src + idx);
                __half2 h0 = __floats2half2_rn(v.x, v.y);
                __half2 h1 = __floats2half2_rn(v.z, v.w);
                uint2 u = { *(unsigned*)&h0, *(unsigned*)&h1 };
                *(uint2*)(xs2 + r * XS2 + 2 * k4) = u;
            }
        }

        // W chunk q: 128 n-rows x 16 kp, linear source, stride-WSN dest
        auto issue_chunk = [&](int q) {
            const unsigned* src = Wg + (size_t)q * (128 * 16);
            unsigned* dst = wsu + (q & (NBUF - 1)) * CH_SM_U;
            #pragma unroll
            for (int j = 0; j < 2; ++j) {
                int idx = tid + j * NTH;            // 512 x 16B segments
                int n = idx >> 2, s4 = (idx & 3) << 2;
                cp16(dst + n * WSN + s4, src + n * 16 + s4);
            }
            cp_commit();
        };

        issue_chunk(0);
        issue_chunk(1);

        #pragma unroll 1
        for (int q = 0; q < NCH; ++q) {
            const int c = q & 7;
            if (q + 2 < NCH) issue_chunk(q + 2);
            if (q < NCH - 2)       cp_wait<2>();
            else if (q == NCH - 2) cp_wait<1>();
            else                   cp_wait<0>();
            __syncthreads();    // chunk q landed; X staged (q==0); MMAs of q-1 done

            if (c == 0) {
                #pragma unroll
                for (int mt = 0; mt < 2; ++mt)
                    #pragma unroll
                    for (int nt = 0; nt < 4; ++nt)
                        #pragma unroll
                        for (int v = 0; v < 4; ++v) ec[mt][nt][v] = 0.f;
            }

            const unsigned slot = (q & (NBUF - 1)) * (CH_SM_U * 4);  // bytes
            unsigned fa[2][8], fb[2][8];

            // preload k16-step 0
            {
                unsigned ka = (c * 16) * 4;
                LDSM4(fa[0][0], fa[0][1], fa[0][2], fa[0][3], addrA[0] + ka);
                LDSM4(fa[0][4], fa[0][5], fa[0][6], fa[0][7], addrA[1] + ka);
                LDSM4(fb[0][0], fb[0][1], fb[0][2], fb[0][3], addrB[0] + slot);
                LDSM4(fb[0][4], fb[0][5], fb[0][6], fb[0][7], addrB[1] + slot);
            }

            #pragma unroll
            for (int kk = 0; kk < 2; ++kk) {
                const int cur = kk & 1;
                if (kk == 0) {      // prefetch k16-step 1
                    unsigned ka = (c * 16 + 8) * 4;
                    LDSM4(fa[1][0], fa[1][1], fa[1][2], fa[1][3], addrA[0] + ka);
                    LDSM4(fa[1][4], fa[1][5], fa[1][6], fa[1][7], addrA[1] + ka);
                    LDSM4(fb[1][0], fb[1][1], fb[1][2], fb[1][3], addrB[0] + slot + 32);
                    LDSM4(fb[1][4], fb[1][5], fb[1][6], fb[1][7], addrB[1] + slot + 32);
                }
                #pragma unroll
                for (int nt = 0; nt < 4; ++nt) {
                    unsigned b0 = fb[cur][(nt >> 1) * 4 + (nt & 1) * 2];
                    unsigned b1 = fb[cur][(nt >> 1) * 4 + (nt & 1) * 2 + 1];
                    #pragma unroll
                    for (int mt = 0; mt < 2; ++mt)
                        mma16(ec[mt][nt][0], ec[mt][nt][1], ec[mt][nt][2], ec[mt][nt][3],
                              fa[cur][mt * 4 + 0], fa[cur][mt * 4 + 1],
                              fa[cur][mt * 4 + 2], fa[cur][mt * 4 + 3], b0, b1);
                }
            }

            if (c == 7) {
                const int e = q >> 3;
                #pragma unroll
                for (int mt = 0; mt < 2; ++mt) {
                    int rl = wm * 32 + mt * 16 + gid;
                    const float* wr0 = wsm + rl * GSS;
                    const float* wr1 = wsm + (rl + 8) * GSS;
                    float wA0 = 0.f, wA1 = 0.f, wB0 = 0.f, wB1 = 0.f, wS0, wS1;
                    if (sg == 0) {
                        wA0 = wr0[e];      wA1 = wr1[e];
                        wS0 = wr0[32 + e]; wS1 = wr1[32 + e];
                    } else if (sg == 1) {
                        wB0 = wr0[16 + e]; wB1 = wr1[16 + e];
                        wS0 = wr0[40 + e]; wS1 = wr1[40 + e];
                    } else {
                        wA0 = wr0[8 + e];  wA1 = wr1[8 + e];
                        wB0 = wr0[24 + e]; wB1 = wr1[24 + e];
                        wS0 = wr0[48 + e]; wS1 = wr1[48 + e];
                    }
                    size_t r0off = (size_t)(row0 + rl) * EXP_D;
                    size_t r1off = (size_t)(row0 + rl + 8) * EXP_D;
                    #pragma unroll
                    for (int nt = 0; nt < 4; ++nt) {
                        int c0 = wn * 32 + nt * 8 + 2 * tig;
                        const float* bp = bsm + sg * 1024 + e * EXP_D + c0;
                        float b0 = bp[0], b1 = bp[1];
                        float t0 = ec[mt][nt][0] + b0, t1 = ec[mt][nt][1] + b1;
                        float t2 = ec[mt][nt][2] + b0, t3 = ec[mt][nt][3] + b1;

                        os[mt][nt][0] += wS0 * t0; os[mt][nt][1] += wS0 * t1;
                        os[mt][nt][2] += wS1 * t2; os[mt][nt][3] += wS1 * t3;

                        if (sg != 1) {   // out_a
                            float2* p0 = (float2*)(out + r0off + c0);
                            float2* p1 = (float2*)(out + r1off + c0);
                            if (sg == 0 && e == 0) {
                                *p0 = make_float2(wA0 * t0, wA0 * t1);
                                *p1 = make_float2(wA1 * t2, wA1 * t3);
                            } else {
                                float2 v0 = *p0, v1 = *p1;
                                v0.x += wA0 * t0; v0.y += wA0 * t1;
                                v1.x += wA1 * t2; v1.y += wA1 * t3;
                                *p0 = v0; *p1 = v1;
                            }
                        }
                        if (sg != 0) {   // out_b
                            float2* p0 = (float2*)(out + OS + r0off + c0);
                            float2* p1 = (float2*)(out + OS + r1off + c0);
                            if (sg == 1 && e == 0) {
                                *p0 = make_float2(wB0 * t0, wB0 * t1);
                                *p1 = make_float2(wB1 * t2, wB1 * t3);
                            } else {
                                float2 v0 = *p0, v1 = *p1;
                                v0.x += wB0 * t0; v0.y += wB0 * t1;
                                v1.x += wB1 * t2; v1.y += wB1 * t3;
                                *p0 = v0; *p1 = v1;
                            }
                        }
                    }
                }
            }
        }
    }

    // ---------------- write out_s ----------------
    #pragma unroll
    for (int mt = 0; mt < 2; ++mt) {
        int r = row0 + wm * 32 + mt * 16 + gid;
        #pragma unroll
        for (int nt = 0; nt < 4; ++nt) {
            int c0 = wn * 32 + nt * 8 + 2 * tig;
            *(float2*)(out + 2 * OS + (size_t)r * EXP_D + c0) =
                make_float2(os[mt][nt][0], os[mt][nt][1]);
            *(float2*)(out + 2 * OS + (size_t)(r + 8) * EXP_D + c0) =
                make_float2(os[mt][nt][2], os[mt][nt][3]);
        }
    }
}

extern "C" void kernel_launch(void* const* d_in, const int* in_sizes, int n_in,
                              void* d_out, int out_size) {
    (void)in_sizes; (void)n_in; (void)out_size;

    w_convert2<<<1536, NTH>>>((const float*)d_in[3], (const float*)d_in[5],
                              (const float*)d_in[7]);

    constexpr int SMEM_BYTES = SMEM_WORDS * 4;   // 101,632 B (2 CTAs/SM co-resident)
    cudaFuncSetAttribute(ple_kernel, cudaFuncAttributeMaxDynamicSharedMemorySize, SMEM_BYTES);
    ple_kernel<<<BT / TB, NTH, SMEM_BYTES>>>(
        (const float*)d_in[0], (const float*)d_in[1], (const float*)d_in[2],
        (const float*)d_in[4], (const float*)d_in[6], (const float*)d_in[8],
        (const float*)d_in[9], (const float*)d_in[10], (const float*)d_in[11],
        (float*)d_out);
}

// round 13
// speedup vs baseline: 1.0814x; 1.0814x over previous
#include <cuda_runtime.h>
#include <cuda_fp16.h>

// PLE layers, round 13: fp16 HMMA + ldmatrix + cp.async.bulk W streaming.
//   Model: LSU issue throughput (cp.async @8cyc/16B) was the binding resource
//   (~40% of runtime); W chunks now arrive via one cp.async.bulk (8KB) per
//   chunk completing on an mbarrier -> zero per-thread LSU cost. Prepass bakes
//   an SW64-style swizzle into the linear chunk image so ldmatrix stays
//   conflict-free. Outputs fully register-resident (R11), 1 CTA x 256 thr.

#define BT      16384
#define IN_D    256
#define EXP_D   128
#define NE      8
#define TB      64
#define NTH     256
#define XSSF    260         // phase-1 fp32 X stride (words)
#define XS2     132         // phase-2 half2 X stride (uints)
#define GSS     57
#define NBUF    4
#define NCHT    192         // total chunks: 3 stacks * 8 experts * 8
#define CH_U    2048        // uints per chunk: 128 n-rows x 16 kp (8 KB)

// smem word offsets
#define OFF_XS   0                            // phase1 fp32 (16640 w) / phase2 half2 (8448 w)
#define OFF_WS   16640                        // W ring: 4 x 2048 w (64B-aligned byte offset)
#define OFF_WSM  (OFF_WS + NBUF*CH_U)         // 24832
#define OFF_BSM  (OFF_WSM + TB*GSS)           // 28480
#define OFF_MB   (OFF_BSM + 3*1024)           // 31552 (4 mbarriers, 8B each)
#define SMEM_WORDS (OFF_MB + 8)               // 31560 words = 126,240 B

#define BSWZ(o) ((o) ^ (((o) >> 3) & 0x30))   // SW64-ish: bits[5:4] ^= bits[8:7]

__device__ __align__(128) unsigned Wc2[NCHT * CH_U];   // pre-swizzled fp16x2 W chunks

__device__ __forceinline__ void bulk_cp(unsigned dst, const void* src, unsigned bytes,
                                        unsigned mbar) {
    asm volatile(
        "cp.async.bulk.shared::cta.global.mbarrier::complete_tx::bytes [%0], [%1], %2, [%3];"
        :: "r"(dst), "l"(src), "r"(bytes), "r"(mbar) : "memory");
}
#define MBAR_INIT(addr, cnt) \
    asm volatile("mbarrier.init.shared.b64 [%0], %1;" :: "r"(addr), "r"(cnt) : "memory")
#define MBAR_EXPECT_TX(addr, bytes) \
    asm volatile("mbarrier.arrive.expect_tx.shared.b64 _, [%0], %1;" \
                 :: "r"(addr), "r"((unsigned)(bytes)) : "memory")

__device__ __forceinline__ void mbar_wait(unsigned addr, unsigned parity) {
    unsigned done;
    asm volatile("{\n .reg .pred p;\n"
                 " mbarrier.try_wait.parity.acquire.cta.shared::cta.b64 p, [%1], %2;\n"
                 " selp.b32 %0, 1, 0, p;\n}"
                 : "=r"(done) : "r"(addr), "r"(parity) : "memory");
    if (!done) {
        asm volatile("{\n .reg .pred P1;\n"
                     "WL_%=:\n"
                     " mbarrier.try_wait.parity.acquire.cta.shared::cta.b64 P1, [%0], %1, 0x989680;\n"
                     " @P1 bra.uni WD_%=;\n"
                     " bra.uni WL_%=;\n"
                     "WD_%=:\n}"
                     :: "r"(addr), "r"(parity) : "memory");
    }
}

#define LDSM4(r0, r1, r2, r3, addr) \
    asm volatile("ldmatrix.sync.aligned.m8n8.x4.shared.b16 {%0,%1,%2,%3}, [%4];" \
                 : "=r"(r0), "=r"(r1), "=r"(r2), "=r"(r3) : "r"(addr))

__device__ __forceinline__ void mma16(float& c0, float& c1, float& c2, float& c3,
                                      unsigned a0, unsigned a1, unsigned a2, unsigned a3,
                                      unsigned b0, unsigned b1) {
    asm volatile(
        "mma.sync.aligned.m16n8k16.row.col.f32.f16.f16.f32 "
        "{%0,%1,%2,%3}, {%4,%5,%6,%7}, {%8,%9}, {%0,%1,%2,%3};\n"
        : "+f"(c0), "+f"(c1), "+f"(c2), "+f"(c3)
        : "r"(a0), "r"(a1), "r"(a2), "r"(a3), "r"(b0), "r"(b1));
}

// ---- prepass: W[e][k][n] -> fp16x2 k-pairs, [sg][e][c] chunk images, swizzle baked ----
__global__ void w_convert2(const float* __restrict__ Wa, const float* __restrict__ Wb,
                           const float* __restrict__ Wsx) {
    int id = blockIdx.x * blockDim.x + threadIdx.x;   // 393216 threads
    int kp = id & 15;
    int n  = (id >> 4) & 127;
    int c  = (id >> 11) & 7;
    int e  = (id >> 14) & 7;
    int sg = id >> 17;
    const float* W = (sg == 0) ? Wa : (sg == 1) ? Wb : Wsx;
    int k = c * 32 + 2 * kp;
    const float* p = W + ((size_t)e * IN_D + k) * EXP_D + n;
    __half2 h = __floats2half2_rn(p[0], p[EXP_D]);    // low = even k
    unsigned o = (unsigned)(n * 64 + kp * 4);         // byte offset in chunk
    int chunk = (sg * 8 + e) * 8 + c;
    *(unsigned*)((char*)(Wc2 + (size_t)chunk * CH_U) + BSWZ(o)) = *(unsigned*)&h;
}

// ---------------- main fused kernel ----------------
__global__ __launch_bounds__(NTH, 1)
void ple_kernel(const float* __restrict__ xa, const float* __restrict__ xb,
                const float* __restrict__ xsh,
                const float* __restrict__ ba, const float* __restrict__ bb,
                const float* __restrict__ bsx,
                const float* __restrict__ Ga, const float* __restrict__ Gb,
                const float* __restrict__ Gq,
                float* __restrict__ out)
{
    extern __shared__ float smem[];
    float*    xsf = smem + OFF_XS;
    unsigned* xs2 = (unsigned*)(smem + OFF_XS);
    float*    wsm = smem + OFF_WSM;
    float*    bsm = smem + OFF_BSM;

    const int tid  = threadIdx.x;
    const int lane = tid & 31;
    const int wid  = tid >> 5;
    const int gid  = lane >> 2;
    const int tig  = lane & 3;
    const int wm   = wid >> 2;                // 0..1
    const int wn   = wid & 3;                 // 0..3
    const int sub  = lane >> 3;
    const int l7   = lane & 7;
    const int row0 = blockIdx.x * TB;

    const unsigned xs2_u = (unsigned)__cvta_generic_to_shared(xs2);
    const unsigned ws_u  = (unsigned)__cvta_generic_to_shared(smem + OFF_WS);
    const unsigned mb_u  = (unsigned)__cvta_generic_to_shared(smem + OFF_MB);

    // ldmatrix lane base addresses
    unsigned addrA[2], addrB[2][2];           // A: [mt]; B: [ntp][kk]
    #pragma unroll
    for (int mt = 0; mt < 2; ++mt) {
        int rowA = wm * 32 + mt * 16 + (sub & 1) * 8 + l7;
        addrA[mt] = xs2_u + (rowA * XS2 + (sub >> 1) * 4) * 4;
    }
    #pragma unroll
    for (int ntp = 0; ntp < 2; ++ntp) {
        int rowB = wn * 32 + ntp * 16 + (sub >> 1) * 8 + l7;
        unsigned o0 = (unsigned)(rowB * 64 + (sub & 1) * 16);
        unsigned s0 = BSWZ(o0);
        addrB[ntp][0] = ws_u + s0;
        addrB[ntp][1] = ws_u + (s0 ^ 32);
    }

    if (tid == 0) {
        #pragma unroll
        for (int s = 0; s < NBUF; ++s) MBAR_INIT(mb_u + s * 8, 1);
    }
    __syncthreads();
    if (tid == 0) {                // prologue: chunks 0,1 land during phase 1
        #pragma unroll
        for (int q = 0; q < 2; ++q) {
            MBAR_EXPECT_TX(mb_u + q * 8, CH_U * 4);
            bulk_cp(ws_u + q * CH_U * 4, Wc2 + (size_t)q * CH_U, CH_U * 4, mb_u + q * 8);
        }
    }

    for (int i = tid; i < 1024; i += NTH) {
        bsm[i]        = __ldg(ba + i);
        bsm[1024 + i] = __ldg(bb + i);
        bsm[2048 + i] = __ldg(bsx + i);
    }

    // ---------------- Phase 1: gate logits + softmax on RAW fp32 X ----------------
    #pragma unroll 1
    for (int sg = 0; sg < 3; ++sg) {
        const float* X = (sg == 0) ? xa : (sg == 1) ? xb : xsh;
        const float* G = (sg == 0) ? Ga : (sg == 1) ? Gb : Gq;
        const int NG   = (sg == 2) ? 24 : 16;
        const int WOFF = sg * 16;

        __syncthreads();
        {
            const float4* src = (const float4*)(X + (size_t)row0 * IN_D);
            #pragma unroll
            for (int j = 0; j < 16; ++j) {
                int idx = tid + j * NTH;
                int r = idx >> 6, s4 = (idx & 63) << 2;
                *(float4*)(xsf + r * XSSF + s4) = __ldg(src + idx);
            }
        }
        __syncthreads();

        for (int idx = tid; idx < TB * NG; idx += NTH) {
            int r = idx / NG, g = idx - r * NG;
            const float4* xp = (const float4*)(xsf + r * XSSF);
            const float4* gp = (const float4*)(G + (size_t)g * IN_D);
            float acc = 0.f;
            #pragma unroll 8
            for (int k = 0; k < IN_D / 4; ++k) {
                float4 xv = xp[k];
                float4 gv = __ldg(gp + k);
                acc += xv.x * gv.x; acc += xv.y * gv.y;
                acc += xv.z * gv.z; acc += xv.w * gv.w;
            }
            wsm[r * GSS + WOFF + g] = acc;
        }
        __syncthreads();

        if (tid < TB) {
            float* wr = wsm + tid * GSS + WOFF;
            float m = wr[0];
            for (int g = 1; g < NG; ++g) m = fmaxf(m, wr[g]);
            float s = 0.f;
            for (int g = 0; g < NG; ++g) { float e = expf(wr[g] - m); wr[g] = e; s += e; }
            float inv = 1.f / s;
            for (int g = 0; g < NG; ++g) wr[g] *= inv;
        }
    }

    // ---------------- Phase 2: fp16 expert GEMMs + register-resident gated folds ----------
    float oa[2][4][4] = {}, ob[2][4][4] = {}, os[2][4][4] = {};
    float ec[2][4][4];

    #pragma unroll 1
    for (int Q = 0; Q < NCHT; ++Q) {
        const int c  = Q & 7;
        const int e  = (Q >> 3) & 7;
        const int sg = Q >> 6;

        if ((Q & 63) == 0) {          // stack boundary: restage X as half2
            __syncthreads();          // protect prior xs2 readers (and phase-1 at Q=0)
            const float* X = (sg == 0) ? xa : (sg == 1) ? xb : xsh;
            const float4* src = (const float4*)(X + (size_t)row0 * IN_D);
            #pragma unroll
            for (int j = 0; j < 16; ++j) {
                int idx = tid + j * NTH;
                int r = idx >> 6, k4 = idx & 63;
                float4 v = __ldg(src + idx);
                __half2 h0 = __floats2half2_rn(v.x, v.y);
                __half2 h1 = __floats2half2_rn(v.z, v.w);
                uint2 u = { *(unsigned*)&h0, *(unsigned*)&h1 };
                *(uint2*)(xs2 + r * XS2 + 2 * k4) = u;
            }
        }

        if (tid == 0 && Q + 2 < NCHT) {    // slot(Q+2)=slot(Q-2): reads done pre-barrier(Q-1)
            int q2 = Q + 2, s2 = q2 & (NBUF - 1);
            MBAR_EXPECT_TX(mb_u + s2 * 8, CH_U * 4);
            bulk_cp(ws_u + s2 * CH_U * 4, Wc2 + (size_t)q2 * CH_U, CH_U * 4, mb_u + s2 * 8);
        }

        __syncthreads();                   // all warps past chunk Q-1; X staged
        mbar_wait(mb_u + (Q & (NBUF - 1)) * 8, (Q >> 2) & 1);   // chunk Q landed

        if (c == 0) {
            #pragma unroll
            for (int mt = 0; mt < 2; ++mt)
                #pragma unroll
                for (int nt = 0; nt < 4; ++nt)
                    #pragma unroll
                    for (int v = 0; v < 4; ++v) ec[mt][nt][v] = 0.f;
        }

        const unsigned slot = (Q & (NBUF - 1)) * (CH_U * 4);   // byte offset in ring
        unsigned fa[2][8], fb[2][8];

        {   // preload k16-step 0
            unsigned ka = (unsigned)(c * 64);
            LDSM4(fa[0][0], fa[0][1], fa[0][2], fa[0][3], addrA[0] + ka);
            LDSM4(fa[0][4], fa[0][5], fa[0][6], fa[0][7], addrA[1] + ka);
            LDSM4(fb[0][0], fb[0][1], fb[0][2], fb[0][3], addrB[0][0] + slot);
            LDSM4(fb[0][4], fb[0][5], fb[0][6], fb[0][7], addrB[1][0] + slot);
        }

        #pragma unroll
        for (int kk = 0; kk < 2; ++kk) {
            const int cur = kk & 1;
            if (kk == 0) {                 // prefetch k16-step 1
                unsigned ka = (unsigned)(c * 64 + 32);
                LDSM4(fa[1][0], fa[1][1], fa[1][2], fa[1][3], addrA[0] + ka);
                LDSM4(fa[1][4], fa[1][5], fa[1][6], fa[1][7], addrA[1] + ka);
                LDSM4(fb[1][0], fb[1][1], fb[1][2], fb[1][3], addrB[0][1] + slot);
                LDSM4(fb[1][4], fb[1][5], fb[1][6], fb[1][7], addrB[1][1] + slot);
            }
            #pragma unroll
            for (int nt = 0; nt < 4; ++nt) {
                unsigned b0 = fb[cur][(nt >> 1) * 4 + (nt & 1) * 2];
                unsigned b1 = fb[cur][(nt >> 1) * 4 + (nt & 1) * 2 + 1];
                #pragma unroll
                for (int mt = 0; mt < 2; ++mt)
                    mma16(ec[mt][nt][0], ec[mt][nt][1], ec[mt][nt][2], ec[mt][nt][3],
                          fa[cur][mt * 4 + 0], fa[cur][mt * 4 + 1],
                          fa[cur][mt * 4 + 2], fa[cur][mt * 4 + 3], b0, b1);
            }
        }

        if (c == 7) {
            #pragma unroll
            for (int mt = 0; mt < 2; ++mt) {
                int rl = wm * 32 + mt * 16 + gid;
                float w1l, w1h, w2l, w2h, w3l = 0.f, w3h = 0.f;
                if (sg == 0) {
                    w1l = wsm[rl * GSS + e];      w1h = wsm[(rl + 8) * GSS + e];
                    w2l = wsm[rl * GSS + 32 + e]; w2h = wsm[(rl + 8) * GSS + 32 + e];
                } else if (sg == 1) {
                    w1l = wsm[rl * GSS + 16 + e]; w1h = wsm[(rl + 8) * GSS + 16 + e];
                    w2l = wsm[rl * GSS + 40 + e]; w2h = wsm[(rl + 8) * GSS + 40 + e];
                } else {
                    w1l = wsm[rl * GSS + 8 + e];  w1h = wsm[(rl + 8) * GSS + 8 + e];
                    w2l = wsm[rl * GSS + 24 + e]; w2h = wsm[(rl + 8) * GSS + 24 + e];
                    w3l = wsm[rl * GSS + 48 + e]; w3h = wsm[(rl + 8) * GSS + 48 + e];
                }
                #pragma unroll
                for (int nt = 0; nt < 4; ++nt) {
                    int c0 = wn * 32 + nt * 8 + 2 * tig;
                    const float* bp = bsm + sg * 1024 + e * EXP_D + c0;
                    float t0 = ec[mt][nt][0] + bp[0];
                    float t1 = ec[mt][nt][1] + bp[1];
                    float t2 = ec[mt][nt][2] + bp[0];
                    float t3 = ec[mt][nt][3] + bp[1];
                    if (sg == 0) {
                        oa[mt][nt][0] += w1l * t0; oa[mt][nt][1] += w1l * t1;
                        oa[mt][nt][2] += w1h * t2; oa[mt][nt][3] += w1h * t3;
                        os[mt][nt][0] += w2l * t0; os[mt][nt][1] += w2l * t1;
                        os[mt][nt][2] += w2h * t2; os[mt][nt][3] += w2h * t3;
                    } else if (sg == 1) {
                        ob[mt][nt][0] += w1l * t0; ob[mt][nt][1] += w1l * t1;
                        ob[mt][nt][2] += w1h * t2; ob[mt][nt][3] += w1h * t3;
                        os[mt][nt][0] += w2l * t0; os[mt][nt][1] += w2l * t1;
                        os[mt][nt][2] += w2h * t2; os[mt][nt][3] += w2h * t3;
                    } else {
                        oa[mt][nt][0] += w1l * t0; oa[mt][nt][1] += w1l * t1;
                        oa[mt][nt][2] += w1h * t2; oa[mt][nt][3] += w1h * t3;
                        ob[mt][nt][0] += w2l * t0; ob[mt][nt][1] += w2l * t1;
                        ob[mt][nt][2] += w2h * t2; ob[mt][nt][3] += w2h * t3;
                        os[mt][nt][0] += w3l * t0; os[mt][nt][1] += w3l * t1;
                        os[mt][nt][2] += w3h * t2; os[mt][nt][3] += w3h * t3;
                    }
                }
            }
        }
    }

    // ---------------- write out: [out_a | out_b | out_s], each [B,128] ----------------
    const size_t OS = (size_t)BT * EXP_D;
    #pragma unroll
    for (int mt = 0; mt < 2; ++mt) {
        int r = row0 + wm * 32 + mt * 16 + gid;
        #pragma unroll
        for (int nt = 0; nt < 4; ++nt) {
            int c0 = wn * 32 + nt * 8 + 2 * tig;
            size_t p0 = (size_t)r * EXP_D + c0;
            size_t p1 = (size_t)(r + 8) * EXP_D + c0;
            *(float2*)(out + p0)          = make_float2(oa[mt][nt][0], oa[mt][nt][1]);
            *(float2*)(out + p1)          = make_float2(oa[mt][nt][2], oa[mt][nt][3]);
            *(float2*)(out + OS + p0)     = make_float2(ob[mt][nt][0], ob[mt][nt][1]);
            *(float2*)(out + OS + p1)     = make_float2(ob[mt][nt][2], ob[mt][nt][3]);
            *(float2*)(out + 2 * OS + p0) = make_float2(os[mt][nt][0], os[mt][nt][1]);
            *(float2*)(out + 2 * OS + p1) = make_float2(os[mt][nt][2], os[mt][nt][3]);
        }
    }
}

extern "C" void kernel_launch(void* const* d_in, const int* in_sizes, int n_in,
                              void* d_out, int out_size) {
    (void)in_sizes; (void)n_in; (void)out_size;

    w_convert2<<<1536, NTH>>>((const float*)d_in[3], (const float*)d_in[5],
                              (const float*)d_in[7]);

    constexpr int SMEM_BYTES = SMEM_WORDS * 4;   // 126,240 B
    cudaFuncSetAttribute(ple_kernel, cudaFuncAttributeMaxDynamicSharedMemorySize, SMEM_BYTES);
    ple_kernel<<<BT / TB, NTH, SMEM_BYTES>>>(
        (const float*)d_in[0], (const float*)d_in[1], (const float*)d_in[2],
        (const float*)d_in[4], (const float*)d_in[6], (const float*)d_in[8],
        (const float*)d_in[9], (const float*)d_in[10], (const float*)d_in[11],
        (float*)d_out);
}

// round 14
// speedup vs baseline: 1.0865x; 1.0047x over previous
#include <cuda_runtime.h>
#include <cuda_fp16.h>

// PLE layers, round 14: fp16 HMMA + ldmatrix + cp.async.bulk, 16 warps/CTA.
//   Diagnosis: serial per-chunk chain (barrier->mbar->LDSM->MMA) exposed by
//   2 warps/SMSP. Fix: 512 thr / warp tile 16x32 halves per-thread state
//   (~110 regs) -> 4 warps/SMSP of latency hiding, no extra gmem traffic.
//   Bulk-DMA W ring at prefetch distance 3; outputs register-resident.

#define BT      16384
#define IN_D    256
#define EXP_D   128
#define NE      8
#define TB      64
#define NTH     512
#define XSSF    260         // phase-1 fp32 X stride (words)
#define XS2     132         // phase-2 half2 X stride (uints)
#define GSS     57
#define NBUF    4
#define NCHT    192         // 3 stacks * 8 experts * 8 chunks
#define CH_U    2048        // uints per chunk: 128 n-rows x 16 kp (8 KB)

// smem word offsets
#define OFF_XS   0
#define OFF_WS   16640                        // W ring: 4 x 2048 w
#define OFF_WSM  (OFF_WS + NBUF*CH_U)         // 24832
#define OFF_BSM  (OFF_WSM + TB*GSS)           // 28480
#define OFF_MB   (OFF_BSM + 3*1024)           // 31552
#define SMEM_WORDS (OFF_MB + 8)               // 126,240 B

#define BSWZ(o) ((o) ^ (((o) >> 3) & 0x30))

__device__ __align__(128) unsigned Wc2[NCHT * CH_U];

__device__ __forceinline__ void bulk_cp(unsigned dst, const void* src, unsigned bytes,
                                        unsigned mbar) {
    asm volatile(
        "cp.async.bulk.shared::cta.global.mbarrier::complete_tx::bytes [%0], [%1], %2, [%3];"
        :: "r"(dst), "l"(src), "r"(bytes), "r"(mbar) : "memory");
}
#define MBAR_INIT(addr, cnt) \
    asm volatile("mbarrier.init.shared.b64 [%0], %1;" :: "r"(addr), "r"(cnt) : "memory")
#define MBAR_EXPECT_TX(addr, bytes) \
    asm volatile("mbarrier.arrive.expect_tx.shared.b64 _, [%0], %1;" \
                 :: "r"(addr), "r"((unsigned)(bytes)) : "memory")

__device__ __forceinline__ void mbar_wait(unsigned addr, unsigned parity) {
    unsigned done;
    asm volatile("{\n .reg .pred p;\n"
                 " mbarrier.try_wait.parity.acquire.cta.shared::cta.b64 p, [%1], %2;\n"
                 " selp.b32 %0, 1, 0, p;\n}"
                 : "=r"(done) : "r"(addr), "r"(parity) : "memory");
    if (!done) {
        asm volatile("{\n .reg .pred P1;\n"
                     "WL_%=:\n"
                     " mbarrier.try_wait.parity.acquire.cta.shared::cta.b64 P1, [%0], %1, 0x989680;\n"
                     " @P1 bra.uni WD_%=;\n"
                     " bra.uni WL_%=;\n"
                     "WD_%=:\n}"
                     :: "r"(addr), "r"(parity) : "memory");
    }
}

#define LDSM4(r0, r1, r2, r3, addr) \
    asm volatile("ldmatrix.sync.aligned.m8n8.x4.shared.b16 {%0,%1,%2,%3}, [%4];" \
                 : "=r"(r0), "=r"(r1), "=r"(r2), "=r"(r3) : "r"(addr))

__device__ __forceinline__ void mma16(float& c0, float& c1, float& c2, float& c3,
                                      unsigned a0, unsigned a1, unsigned a2, unsigned a3,
                                      unsigned b0, unsigned b1) {
    asm volatile(
        "mma.sync.aligned.m16n8k16.row.col.f32.f16.f16.f32 "
        "{%0,%1,%2,%3}, {%4,%5,%6,%7}, {%8,%9}, {%0,%1,%2,%3};\n"
        : "+f"(c0), "+f"(c1), "+f"(c2), "+f"(c3)
        : "r"(a0), "r"(a1), "r"(a2), "r"(a3), "r"(b0), "r"(b1));
}

// ---- prepass: W[e][k][n] -> fp16x2 k-pairs, chunk images with baked swizzle ----
__global__ void w_convert2(const float* __restrict__ Wa, const float* __restrict__ Wb,
                           const float* __restrict__ Wsx) {
    int id = blockIdx.x * blockDim.x + threadIdx.x;
    int kp = id & 15;
    int n  = (id >> 4) & 127;
    int c  = (id >> 11) & 7;
    int e  = (id >> 14) & 7;
    int sg = id >> 17;
    const float* W = (sg == 0) ? Wa : (sg == 1) ? Wb : Wsx;
    int k = c * 32 + 2 * kp;
    const float* p = W + ((size_t)e * IN_D + k) * EXP_D + n;
    __half2 h = __floats2half2_rn(p[0], p[EXP_D]);
    unsigned o = (unsigned)(n * 64 + kp * 4);
    int chunk = (sg * 8 + e) * 8 + c;
    *(unsigned*)((char*)(Wc2 + (size_t)chunk * CH_U) + BSWZ(o)) = *(unsigned*)&h;
}

// ---------------- main fused kernel ----------------
__global__ __launch_bounds__(NTH, 1)
void ple_kernel(const float* __restrict__ xa, const float* __restrict__ xb,
                const float* __restrict__ xsh,
                const float* __restrict__ ba, const float* __restrict__ bb,
                const float* __restrict__ bsx,
                const float* __restrict__ Ga, const float* __restrict__ Gb,
                const float* __restrict__ Gq,
                float* __restrict__ out)
{
    extern __shared__ float smem[];
    float*    xsf = smem + OFF_XS;
    unsigned* xs2 = (unsigned*)(smem + OFF_XS);
    float*    wsm = smem + OFF_WSM;
    float*    bsm = smem + OFF_BSM;

    const int tid  = threadIdx.x;
    const int lane = tid & 31;
    const int wid  = tid >> 5;
    const int gid  = lane >> 2;
    const int tig  = lane & 3;
    const int wm   = wid >> 2;                // 0..3 (16-row band)
    const int wn   = wid & 3;                 // 0..3 (32-col band)
    const int sub  = lane >> 3;
    const int l7   = lane & 7;
    const int row0 = blockIdx.x * TB;

    const unsigned xs2_u = (unsigned)__cvta_generic_to_shared(xs2);
    const unsigned ws_u  = (unsigned)__cvta_generic_to_shared(smem + OFF_WS);
    const unsigned mb_u  = (unsigned)__cvta_generic_to_shared(smem + OFF_MB);

    // ldmatrix lane base addresses
    unsigned addrA, addrB[2][2];              // A: warp tile 16 rows; B: [ntp][kk]
    {
        int rowA = wm * 16 + (sub & 1) * 8 + l7;
        addrA = xs2_u + (rowA * XS2 + (sub >> 1) * 4) * 4;
    }
    #pragma unroll
    for (int ntp = 0; ntp < 2; ++ntp) {
        int rowB = wn * 32 + ntp * 16 + (sub >> 1) * 8 + l7;
        unsigned o0 = (unsigned)(rowB * 64 + (sub & 1) * 16);
        unsigned s0 = BSWZ(o0);
        addrB[ntp][0] = ws_u + s0;
        addrB[ntp][1] = ws_u + (s0 ^ 32);
    }

    if (tid == 0) {
        #pragma unroll
        for (int s = 0; s < NBUF; ++s) MBAR_INIT(mb_u + s * 8, 1);
    }
    __syncthreads();
    if (tid == 0) {                // prologue: chunks 0..2 land during phase 1
        #pragma unroll
        for (int q = 0; q < 3; ++q) {
            MBAR_EXPECT_TX(mb_u + q * 8, CH_U * 4);
            bulk_cp(ws_u + q * CH_U * 4, Wc2 + (size_t)q * CH_U, CH_U * 4, mb_u + q * 8);
        }
    }

    for (int i = tid; i < 1024; i += NTH) {
        bsm[i]        = __ldg(ba + i);
        bsm[1024 + i] = __ldg(bb + i);
        bsm[2048 + i] = __ldg(bsx + i);
    }

    // ---------------- Phase 1: gate logits + softmax on RAW fp32 X ----------------
    #pragma unroll 1
    for (int sg = 0; sg < 3; ++sg) {
        const float* X = (sg == 0) ? xa : (sg == 1) ? xb : xsh;
        const float* G = (sg == 0) ? Ga : (sg == 1) ? Gb : Gq;
        const int NG   = (sg == 2) ? 24 : 16;
        const int WOFF = sg * 16;

        __syncthreads();
        {
            const float4* src = (const float4*)(X + (size_t)row0 * IN_D);
            #pragma unroll
            for (int j = 0; j < 8; ++j) {
                int idx = tid + j * NTH;               // 4096 float4
                int r = idx >> 6, s4 = (idx & 63) << 2;
                *(float4*)(xsf + r * XSSF + s4) = __ldg(src + idx);
            }
        }
        __syncthreads();

        for (int idx = tid; idx < TB * NG; idx += NTH) {
            int r = idx / NG, g = idx - r * NG;
            const float4* xp = (const float4*)(xsf + r * XSSF);
            const float4* gp = (const float4*)(G + (size_t)g * IN_D);
            float acc = 0.f;
            #pragma unroll 8
            for (int k = 0; k < IN_D / 4; ++k) {
                float4 xv = xp[k];
                float4 gv = __ldg(gp + k);
                acc += xv.x * gv.x; acc += xv.y * gv.y;
                acc += xv.z * gv.z; acc += xv.w * gv.w;
            }
            wsm[r * GSS + WOFF + g] = acc;
        }
        __syncthreads();

        if (tid < TB) {
            float* wr = wsm + tid * GSS + WOFF;
            float m = wr[0];
            for (int g = 1; g < NG; ++g) m = fmaxf(m, wr[g]);
            float s = 0.f;
            for (int g = 0; g < NG; ++g) { float e = expf(wr[g] - m); wr[g] = e; s += e; }
            float inv = 1.f / s;
            for (int g = 0; g < NG; ++g) wr[g] *= inv;
        }
    }

    // ---------------- Phase 2: fp16 expert GEMMs + register-resident folds ----------------
    float oa[4][4] = {}, ob[4][4] = {}, os[4][4] = {};
    float ec[4][4];

    #pragma unroll 1
    for (int Q = 0; Q < NCHT; ++Q) {
        const int c  = Q & 7;
        const int e  = (Q >> 3) & 7;
        const int sg = Q >> 6;

        if ((Q & 63) == 0) {          // stack boundary: restage X as half2
            __syncthreads();
            const float* X = (sg == 0) ? xa : (sg == 1) ? xb : xsh;
            const float4* src = (const float4*)(X + (size_t)row0 * IN_D);
            #pragma unroll
            for (int j = 0; j < 8; ++j) {
                int idx = tid + j * NTH;               // 4096 float4
                int r = idx >> 6, k4 = idx & 63;
                float4 v = __ldg(src + idx);
                __half2 h0 = __floats2half2_rn(v.x, v.y);
                __half2 h1 = __floats2half2_rn(v.z, v.w);
                uint2 u = { *(unsigned*)&h0, *(unsigned*)&h1 };
                *(uint2*)(xs2 + r * XS2 + 2 * k4) = u;
            }
        }

        if (tid == 0 && Q + 3 < NCHT) {   // slot(Q+3)=slot(Q-1): reads done pre-barrier
            int q3 = Q + 3, s3 = q3 & (NBUF - 1);
            MBAR_EXPECT_TX(mb_u + s3 * 8, CH_U * 4);
            bulk_cp(ws_u + s3 * CH_U * 4, Wc2 + (size_t)q3 * CH_U, CH_U * 4, mb_u + s3 * 8);
        }

        __syncthreads();                   // all warps past chunk Q-1; X staged
        mbar_wait(mb_u + (Q & (NBUF - 1)) * 8, (Q >> 2) & 1);

        if (c == 0) {
            #pragma unroll
            for (int nt = 0; nt < 4; ++nt)
                #pragma unroll
                for (int v = 0; v < 4; ++v) ec[nt][v] = 0.f;
        }

        const unsigned slot = (Q & (NBUF - 1)) * (CH_U * 4);
        unsigned fa[2][4], fb[2][8];

        {   // preload k16-step 0
            unsigned ka = (unsigned)(c * 64);
            LDSM4(fa[0][0], fa[0][1], fa[0][2], fa[0][3], addrA + ka);
            LDSM4(fb[0][0], fb[0][1], fb[0][2], fb[0][3], addrB[0][0] + slot);
            LDSM4(fb[0][4], fb[0][5], fb[0][6], fb[0][7], addrB[1][0] + slot);
        }

        #pragma unroll
        for (int kk = 0; kk < 2; ++kk) {
            const int cur = kk & 1;
            if (kk == 0) {                 // prefetch k16-step 1
                unsigned ka = (unsigned)(c * 64 + 32);
                LDSM4(fa[1][0], fa[1][1], fa[1][2], fa[1][3], addrA + ka);
                LDSM4(fb[1][0], fb[1][1], fb[1][2], fb[1][3], addrB[0][1] + slot);
                LDSM4(fb[1][4], fb[1][5], fb[1][6], fb[1][7], addrB[1][1] + slot);
            }
            #pragma unroll
            for (int nt = 0; nt < 4; ++nt) {
                unsigned b0 = fb[cur][(nt >> 1) * 4 + (nt & 1) * 2];
                unsigned b1 = fb[cur][(nt >> 1) * 4 + (nt & 1) * 2 + 1];
                mma16(ec[nt][0], ec[nt][1], ec[nt][2], ec[nt][3],
                      fa[cur][0], fa[cur][1], fa[cur][2], fa[cur][3], b0, b1);
            }
        }

        if (c == 7) {
            int rl = wm * 16 + gid;
            float w1l, w1h, w2l, w2h, w3l = 0.f, w3h = 0.f;
            if (sg == 0) {
                w1l = wsm[rl * GSS + e];      w1h = wsm[(rl + 8) * GSS + e];
                w2l = wsm[rl * GSS + 32 + e]; w2h = wsm[(rl + 8) * GSS + 32 + e];
            } else if (sg == 1) {
                w1l = wsm[rl * GSS + 16 + e]; w1h = wsm[(rl + 8) * GSS + 16 + e];
                w2l = wsm[rl * GSS + 40 + e]; w2h = wsm[(rl + 8) * GSS + 40 + e];
            } else {
                w1l = wsm[rl * GSS + 8 + e];  w1h = wsm[(rl + 8) * GSS + 8 + e];
                w2l = wsm[rl * GSS + 24 + e]; w2h = wsm[(rl + 8) * GSS + 24 + e];
                w3l = wsm[rl * GSS + 48 + e]; w3h = wsm[(rl + 8) * GSS + 48 + e];
            }
            #pragma unroll
            for (int nt = 0; nt < 4; ++nt) {
                int c0 = wn * 32 + nt * 8 + 2 * tig;
                const float* bp = bsm + sg * 1024 + e * EXP_D + c0;
                float t0 = ec[nt][0] + bp[0];
                float t1 = ec[nt][1] + bp[1];
                float t2 = ec[nt][2] + bp[0];
                float t3 = ec[nt][3] + bp[1];
                if (sg == 0) {
                    oa[nt][0] += w1l * t0; oa[nt][1] += w1l * t1;
                    oa[nt][2] += w1h * t2; oa[nt][3] += w1h * t3;
                    os[nt][0] += w2l * t0; os[nt][1] += w2l * t1;
                    os[nt][2] += w2h * t2; os[nt][3] += w2h * t3;
                } else if (sg == 1) {
                    ob[nt][0] += w1l * t0; ob[nt][1] += w1l * t1;
                    ob[nt][2] += w1h * t2; ob[nt][3] += w1h * t3;
                    os[nt][0] += w2l * t0; os[nt][1] += w2l * t1;
                    os[nt][2] += w2h * t2; os[nt][3] += w2h * t3;
                } else {
                    oa[nt][0] += w1l * t0; oa[nt][1] += w1l * t1;
                    oa[nt][2] += w1h * t2; oa[nt][3] += w1h * t3;
                    ob[nt][0] += w2l * t0; ob[nt][1] += w2l * t1;
                    ob[nt][2] += w2h * t2; ob[nt][3] += w2h * t3;
                    os[nt][0] += w3l * t0; os[nt][1] += w3l * t1;
                    os[nt][2] += w3h * t2; os[nt][3] += w3h * t3;
                }
            }
        }
    }

    // ---------------- write out: [out_a | out_b | out_s], each [B,128] ----------------
    const size_t OS = (size_t)BT * EXP_D;
    {
        int r = row0 + wm * 16 + gid;
        #pragma unroll
        for (int nt = 0; nt < 4; ++nt) {
            int c0 = wn * 32 + nt * 8 + 2 * tig;
            size_t p0 = (size_t)r * EXP_D + c0;
            size_t p1 = (size_t)(r + 8) * EXP_D + c0;
            *(float2*)(out + p0)          = make_float2(oa[nt][0], oa[nt][1]);
            *(float2*)(out + p1)          = make_float2(oa[nt][2], oa[nt][3]);
            *(float2*)(out + OS + p0)     = make_float2(ob[nt][0], ob[nt][1]);
            *(float2*)(out + OS + p1)     = make_float2(ob[nt][2], ob[nt][3]);
            *(float2*)(out + 2 * OS + p0) = make_float2(os[nt][0], os[nt][1]);
            *(float2*)(out + 2 * OS + p1) = make_float2(os[nt][2], os[nt][3]);
        }
    }
}

extern "C" void kernel_launch(void* const* d_in, const int* in_sizes, int n_in,
                              void* d_out, int out_size) {
    (void)in_sizes; (void)n_in; (void)out_size;

    w_convert2<<<1536, 256>>>((const float*)d_in[3], (const float*)d_in[5],
                              (const float*)d_in[7]);

    constexpr int SMEM_BYTES = SMEM_WORDS * 4;   // 126,240 B
    cudaFuncSetAttribute(ple_kernel, cudaFuncAttributeMaxDynamicSharedMemorySize, SMEM_BYTES);
    ple_kernel<<<BT / TB, NTH, SMEM_BYTES>>>(
        (const float*)d_in[0], (const float*)d_in[1], (const float*)d_in[2],
        (const float*)d_in[4], (const float*)d_in[6], (const float*)d_in[8],
        (const float*)d_in[9], (const float*)d_in[10], (const float*)d_in[11],
        (float*)d_out);
}

// round 15
// speedup vs baseline: 1.1737x; 1.0803x over previous
#include <cuda_runtime.h>
#include <cuda_fp16.h>

// PLE layers, round 15: fp16 HMMA with fp16 ACCUMULATORS (per-chunk fp32
// promotion) + group-of-4 chunk pipeline on an 8-slot cp.async.bulk ring.
//   Evidence: m16n8k16.f32-accum is rate-walled at ~76 cyc/SMSP across all
//   configs; f16-accum historically runs 2x on the throughput path. K=32
//   fp16 accumulation bounds rounding to ~2e-4 abs. CTA barriers cut 192->48.

#define BT      16384
#define IN_D    256
#define EXP_D   128
#define NE      8
#define TB      64
#define NTH     512
#define XSSF    260         // phase-1 fp32 X stride (words)
#define XS2     132         // phase-2 half2 X stride (uints)
#define GSS     57
#define NBUF    8
#define NGRP    48          // groups of 4 chunks (192 chunks total)
#define CH_U    2048        // uints per chunk: 128 n-rows x 16 kp (8 KB)

// smem word offsets
#define OFF_XS   0
#define OFF_WS   16640                        // ring: 8 x 2048 w (64 KB)
#define OFF_WSM  (OFF_WS + NBUF*CH_U)         // 33024
#define OFF_BSM  (OFF_WSM + TB*GSS)           // 36672
#define OFF_MB   (OFF_BSM + 3*1024)           // 39744 (8 mbarriers)
#define SMEM_WORDS (OFF_MB + 16)              // 39760 w = 159,040 B

#define BSWZ(o) ((o) ^ (((o) >> 3) & 0x30))

__device__ __align__(128) unsigned Wc2[NGRP * 4 * CH_U];

__device__ __forceinline__ void bulk_cp(unsigned dst, const void* src, unsigned bytes,
                                        unsigned mbar) {
    asm volatile(
        "cp.async.bulk.shared::cta.global.mbarrier::complete_tx::bytes [%0], [%1], %2, [%3];"
        :: "r"(dst), "l"(src), "r"(bytes), "r"(mbar) : "memory");
}
#define MBAR_INIT(addr, cnt) \
    asm volatile("mbarrier.init.shared.b64 [%0], %1;" :: "r"(addr), "r"(cnt) : "memory")
#define MBAR_EXPECT_TX(addr, bytes) \
    asm volatile("mbarrier.arrive.expect_tx.shared.b64 _, [%0], %1;" \
                 :: "r"(addr), "r"((unsigned)(bytes)) : "memory")

__device__ __forceinline__ void mbar_wait(unsigned addr, unsigned parity) {
    unsigned done;
    asm volatile("{\n .reg .pred p;\n"
                 " mbarrier.try_wait.parity.acquire.cta.shared::cta.b64 p, [%1], %2;\n"
                 " selp.b32 %0, 1, 0, p;\n}"
                 : "=r"(done) : "r"(addr), "r"(parity) : "memory");
    if (!done) {
        asm volatile("{\n .reg .pred P1;\n"
                     "WL_%=:\n"
                     " mbarrier.try_wait.parity.acquire.cta.shared::cta.b64 P1, [%0], %1, 0x989680;\n"
                     " @P1 bra.uni WD_%=;\n"
                     " bra.uni WL_%=;\n"
                     "WD_%=:\n}"
                     :: "r"(addr), "r"(parity) : "memory");
    }
}

#define LDSM4(r0, r1, r2, r3, addr) \
    asm volatile("ldmatrix.sync.aligned.m8n8.x4.shared.b16 {%0,%1,%2,%3}, [%4];" \
                 : "=r"(r0), "=r"(r1), "=r"(r2), "=r"(r3) : "r"(addr))

// fp16-accumulator HMMA: D(f16x2 pair) = A*B + D
__device__ __forceinline__ void mma16h(unsigned& d0, unsigned& d1,
                                       unsigned a0, unsigned a1, unsigned a2, unsigned a3,
                                       unsigned b0, unsigned b1) {
    asm volatile(
        "mma.sync.aligned.m16n8k16.row.col.f16.f16.f16.f16 "
        "{%0,%1}, {%2,%3,%4,%5}, {%6,%7}, {%0,%1};\n"
        : "+r"(d0), "+r"(d1)
        : "r"(a0), "r"(a1), "r"(a2), "r"(a3), "r"(b0), "r"(b1));
}

// ---- prepass: W[e][k][n] -> fp16x2 k-pairs, chunk images with baked swizzle ----
__global__ void w_convert2(const float* __restrict__ Wa, const float* __restrict__ Wb,
                           const float* __restrict__ Wsx) {
    int id = blockIdx.x * blockDim.x + threadIdx.x;
    int kp = id & 15;
    int n  = (id >> 4) & 127;
    int c  = (id >> 11) & 7;
    int e  = (id >> 14) & 7;
    int sg = id >> 17;
    const float* W = (sg == 0) ? Wa : (sg == 1) ? Wb : Wsx;
    int k = c * 32 + 2 * kp;
    const float* p = W + ((size_t)e * IN_D + k) * EXP_D + n;
    __half2 h = __floats2half2_rn(p[0], p[EXP_D]);
    unsigned o = (unsigned)(n * 64 + kp * 4);
    int chunk = (sg * 8 + e) * 8 + c;
    *(unsigned*)((char*)(Wc2 + (size_t)chunk * CH_U) + BSWZ(o)) = *(unsigned*)&h;
}

// ---------------- main fused kernel ----------------
__global__ __launch_bounds__(NTH, 1)
void ple_kernel(const float* __restrict__ xa, const float* __restrict__ xb,
                const float* __restrict__ xsh,
                const float* __restrict__ ba, const float* __restrict__ bb,
                const float* __restrict__ bsx,
                const float* __restrict__ Ga, const float* __restrict__ Gb,
                const float* __restrict__ Gq,
                float* __restrict__ out)
{
    extern __shared__ float smem[];
    float*    xsf = smem + OFF_XS;
    unsigned* xs2 = (unsigned*)(smem + OFF_XS);
    float*    wsm = smem + OFF_WSM;
    float*    bsm = smem + OFF_BSM;

    const int tid  = threadIdx.x;
    const int lane = tid & 31;
    const int wid  = tid >> 5;
    const int gid  = lane >> 2;
    const int tig  = lane & 3;
    const int wm   = wid >> 2;                // 0..3 (16-row band)
    const int wn   = wid & 3;                 // 0..3 (32-col band)
    const int sub  = lane >> 3;
    const int l7   = lane & 7;
    const int row0 = blockIdx.x * TB;

    const unsigned xs2_u = (unsigned)__cvta_generic_to_shared(xs2);
    const unsigned ws_u  = (unsigned)__cvta_generic_to_shared(smem + OFF_WS);
    const unsigned mb_u  = (unsigned)__cvta_generic_to_shared(smem + OFF_MB);

    // ldmatrix lane base addresses
    unsigned addrA, addrB[2][2];              // A: 16-row warp band; B: [ntp][kk]
    {
        int rowA = wm * 16 + (sub & 1) * 8 + l7;
        addrA = xs2_u + (rowA * XS2 + (sub >> 1) * 4) * 4;
    }
    #pragma unroll
    for (int ntp = 0; ntp < 2; ++ntp) {
        int rowB = wn * 32 + ntp * 16 + (sub >> 1) * 8 + l7;
        unsigned o0 = (unsigned)(rowB * 64 + (sub & 1) * 16);
        unsigned s0 = BSWZ(o0);
        addrB[ntp][0] = ws_u + s0;
        addrB[ntp][1] = ws_u + (s0 ^ 32);
    }

    // producer helper: one group = 4 chunks into ring half (G&1)
    auto issue_group = [&](int G) {
        #pragma unroll
        for (int i = 0; i < 4; ++i) {
            int Q = G * 4 + i;
            int s = ((G & 1) << 2) + i;
            MBAR_EXPECT_TX(mb_u + s * 8, CH_U * 4);
            bulk_cp(ws_u + s * CH_U * 4, Wc2 + (size_t)Q * CH_U, CH_U * 4, mb_u + s * 8);
        }
    };

    if (tid == 0) {
        #pragma unroll
        for (int s = 0; s < NBUF; ++s) MBAR_INIT(mb_u + s * 8, 1);
    }
    __syncthreads();
    if (tid == 0) { issue_group(0); issue_group(1); }   // land during phase 1

    for (int i = tid; i < 1024; i += NTH) {
        bsm[i]        = __ldg(ba + i);
        bsm[1024 + i] = __ldg(bb + i);
        bsm[2048 + i] = __ldg(bsx + i);
    }

    // ---------------- Phase 1: gate logits + softmax on RAW fp32 X ----------------
    #pragma unroll 1
    for (int sg = 0; sg < 3; ++sg) {
        const float* X = (sg == 0) ? xa : (sg == 1) ? xb : xsh;
        const float* G = (sg == 0) ? Ga : (sg == 1) ? Gb : Gq;
        const int NG   = (sg == 2) ? 24 : 16;
        const int WOFF = sg * 16;

        __syncthreads();
        {
            const float4* src = (const float4*)(X + (size_t)row0 * IN_D);
            #pragma unroll
            for (int j = 0; j < 8; ++j) {
                int idx = tid + j * NTH;
                int r = idx >> 6, s4 = (idx & 63) << 2;
                *(float4*)(xsf + r * XSSF + s4) = __ldg(src + idx);
            }
        }
        __syncthreads();

        for (int idx = tid; idx < TB * NG; idx += NTH) {
            int r = idx / NG, g = idx - r * NG;
            const float4* xp = (const float4*)(xsf + r * XSSF);
            const float4* gp = (const float4*)(G + (size_t)g * IN_D);
            float acc = 0.f;
            #pragma unroll 8
            for (int k = 0; k < IN_D / 4; ++k) {
                float4 xv = xp[k];
                float4 gv = __ldg(gp + k);
                acc += xv.x * gv.x; acc += xv.y * gv.y;
                acc += xv.z * gv.z; acc += xv.w * gv.w;
            }
            wsm[r * GSS + WOFF + g] = acc;
        }
        __syncthreads();

        if (tid < TB) {
            float* wr = wsm + tid * GSS + WOFF;
            float m = wr[0];
            for (int g = 1; g < NG; ++g) m = fmaxf(m, wr[g]);
            float s = 0.f;
            for (int g = 0; g < NG; ++g) { float e = expf(wr[g] - m); wr[g] = e; s += e; }
            float inv = 1.f / s;
            for (int g = 0; g < NG; ++g) wr[g] *= inv;
        }
    }

    // ---------------- Phase 2: fp16-accum expert GEMMs, group-of-4 pipeline ----------
    float oa[4][4] = {}, ob[4][4] = {}, os[4][4] = {};
    float ec[4][4];

    #pragma unroll 1
    for (int g = 0; g < NGRP; ++g) {
        __syncthreads();                       // group boundary: half (g+1)&1 is free
        if (tid == 0 && g >= 1 && g + 1 < NGRP) issue_group(g + 1);

        if ((g & 15) == 0) {                   // stack boundary: restage X as half2
            const int sgk = g >> 4;
            const float* X = (sgk == 0) ? xa : (sgk == 1) ? xb : xsh;
            const float4* src = (const float4*)(X + (size_t)row0 * IN_D);
            #pragma unroll
            for (int j = 0; j < 8; ++j) {
                int idx = tid + j * NTH;
                int r = idx >> 6, k4 = idx & 63;
                float4 v = __ldg(src + idx);
                __half2 h0 = __floats2half2_rn(v.x, v.y);
                __half2 h1 = __floats2half2_rn(v.z, v.w);
                uint2 u = { *(unsigned*)&h0, *(unsigned*)&h1 };
                *(uint2*)(xs2 + r * XS2 + 2 * k4) = u;
            }
            __syncthreads();
        }

        #pragma unroll
        for (int i = 0; i < 4; ++i) {
            const int Q = g * 4 + i;
            const int c = Q & 7;
            const int slot = ((g & 1) << 2) + i;
            mbar_wait(mb_u + slot * 8, (g >> 1) & 1);

            if (c == 0) {
                #pragma unroll
                for (int nt = 0; nt < 4; ++nt)
                    #pragma unroll
                    for (int v = 0; v < 4; ++v) ec[nt][v] = 0.f;
            }

            const unsigned sb = (unsigned)slot * (CH_U * 4);
            unsigned fa[2][4], fb[8];
            unsigned hc[4][2];
            #pragma unroll
            for (int nt = 0; nt < 4; ++nt) { hc[nt][0] = 0u; hc[nt][1] = 0u; }

            {   // A fragments for both k16 steps, B for step 0
                unsigned ka = (unsigned)(c * 64);
                LDSM4(fa[0][0], fa[0][1], fa[0][2], fa[0][3], addrA + ka);
                LDSM4(fa[1][0], fa[1][1], fa[1][2], fa[1][3], addrA + ka + 32);
                LDSM4(fb[0], fb[1], fb[2], fb[3], addrB[0][0] + sb);
                LDSM4(fb[4], fb[5], fb[6], fb[7], addrB[1][0] + sb);
            }
            #pragma unroll
            for (int nt = 0; nt < 4; ++nt) {
                unsigned b0 = fb[(nt >> 1) * 4 + (nt & 1) * 2];
                unsigned b1 = fb[(nt >> 1) * 4 + (nt & 1) * 2 + 1];
                mma16h(hc[nt][0], hc[nt][1],
                       fa[0][0], fa[0][1], fa[0][2], fa[0][3], b0, b1);
            }
            {   // B for step 1 (WAR on fb after step-0 MMAs issued)
                LDSM4(fb[0], fb[1], fb[2], fb[3], addrB[0][1] + sb);
                LDSM4(fb[4], fb[5], fb[6], fb[7], addrB[1][1] + sb);
            }
            #pragma unroll
            for (int nt = 0; nt < 4; ++nt) {
                unsigned b0 = fb[(nt >> 1) * 4 + (nt & 1) * 2];
                unsigned b1 = fb[(nt >> 1) * 4 + (nt & 1) * 2 + 1];
                mma16h(hc[nt][0], hc[nt][1],
                       fa[1][0], fa[1][1], fa[1][2], fa[1][3], b0, b1);
            }
            // promote chunk partial (K=32, fp16) into fp32 accumulators
            #pragma unroll
            for (int nt = 0; nt < 4; ++nt) {
                __half2 hlo, hhi;
                *(unsigned*)&hlo = hc[nt][0];
                *(unsigned*)&hhi = hc[nt][1];
                float2 lo = __half22float2(hlo);
                float2 hi = __half22float2(hhi);
                ec[nt][0] += lo.x; ec[nt][1] += lo.y;
                ec[nt][2] += hi.x; ec[nt][3] += hi.y;
            }

            if (c == 7) {   // fold expert e of stack sgk
                const int e = (Q >> 3) & 7;
                const int sgk = Q >> 6;
                int rl = wm * 16 + gid;
                float w1l, w1h, w2l, w2h, w3l = 0.f, w3h = 0.f;
                if (sgk == 0) {
                    w1l = wsm[rl * GSS + e];      w1h = wsm[(rl + 8) * GSS + e];
                    w2l = wsm[rl * GSS + 32 + e]; w2h = wsm[(rl + 8) * GSS + 32 + e];
                } else if (sgk == 1) {
                    w1l = wsm[rl * GSS + 16 + e]; w1h = wsm[(rl + 8) * GSS + 16 + e];
                    w2l = wsm[rl * GSS + 40 + e]; w2h = wsm[(rl + 8) * GSS + 40 + e];
                } else {
                    w1l = wsm[rl * GSS + 8 + e];  w1h = wsm[(rl + 8) * GSS + 8 + e];
                    w2l = wsm[rl * GSS + 24 + e]; w2h = wsm[(rl + 8) * GSS + 24 + e];
                    w3l = wsm[rl * GSS + 48 + e]; w3h = wsm[(rl + 8) * GSS + 48 + e];
                }
                #pragma unroll
                for (int nt = 0; nt < 4; ++nt) {
                    int c0 = wn * 32 + nt * 8 + 2 * tig;
                    const float* bp = bsm + sgk * 1024 + e * EXP_D + c0;
                    float t0 = ec[nt][0] + bp[0];
                    float t1 = ec[nt][1] + bp[1];
                    float t2 = ec[nt][2] + bp[0];
                    float t3 = ec[nt][3] + bp[1];
                    if (sgk == 0) {
                        oa[nt][0] += w1l * t0; oa[nt][1] += w1l * t1;
                        oa[nt][2] += w1h * t2; oa[nt][3] += w1h * t3;
                        os[nt][0] += w2l * t0; os[nt][1] += w2l * t1;
                        os[nt][2] += w2h * t2; os[nt][3] += w2h * t3;
                    } else if (sgk == 1) {
                        ob[nt][0] += w1l * t0; ob[nt][1] += w1l * t1;
                        ob[nt][2] += w1h * t2; ob[nt][3] += w1h * t3;
                        os[nt][0] += w2l * t0; os[nt][1] += w2l * t1;
                        os[nt][2] += w2h * t2; os[nt][3] += w2h * t3;
                    } else {
                        oa[nt][0] += w1l * t0; oa[nt][1] += w1l * t1;
                        oa[nt][2] += w1h * t2; oa[nt][3] += w1h * t3;
                        ob[nt][0] += w2l * t0; ob[nt][1] += w2l * t1;
                        ob[nt][2] += w2h * t2; ob[nt][3] += w2h * t3;
                        os[nt][0] += w3l * t0; os[nt][1] += w3l * t1;
                        os[nt][2] += w3h * t2; os[nt][3] += w3h * t3;
                    }
                }
            }
        }
    }

    // ---------------- write out: [out_a | out_b | out_s], each [B,128] ----------------
    const size_t OS = (size_t)BT * EXP_D;
    {
        int r = row0 + wm * 16 + gid;
        #pragma unroll
        for (int nt = 0; nt < 4; ++nt) {
            int c0 = wn * 32 + nt * 8 + 2 * tig;
            size_t p0 = (size_t)r * EXP_D + c0;
            size_t p1 = (size_t)(r + 8) * EXP_D + c0;
            *(float2*)(out + p0)          = make_float2(oa[nt][0], oa[nt][1]);
            *(float2*)(out + p1)          = make_float2(oa[nt][2], oa[nt][3]);
            *(float2*)(out + OS + p0)     = make_float2(ob[nt][0], ob[nt][1]);
            *(float2*)(out + OS + p1)     = make_float2(ob[nt][2], ob[nt][3]);
            *(float2*)(out + 2 * OS + p0) = make_float2(os[nt][0], os[nt][1]);
            *(float2*)(out + 2 * OS + p1) = make_float2(os[nt][2], os[nt][3]);
        }
    }
}

extern "C" void kernel_launch(void* const* d_in, const int* in_sizes, int n_in,
                              void* d_out, int out_size) {
    (void)in_sizes; (void)n_in; (void)out_size;

    w_convert2<<<1536, 256>>>((const float*)d_in[3], (const float*)d_in[5],
                              (const float*)d_in[7]);

    constexpr int SMEM_BYTES = SMEM_WORDS * 4;   // 159,040 B
    cudaFuncSetAttribute(ple_kernel, cudaFuncAttributeMaxDynamicSharedMemorySize, SMEM_BYTES);
    ple_kernel<<<BT / TB, NTH, SMEM_BYTES>>>(
        (const float*)d_in[0], (const float*)d_in[1], (const float*)d_in[2],
        (const float*)d_in[4], (const float*)d_in[6], (const float*)d_in[8],
        (const float*)d_in[9], (const float*)d_in[10], (const float*)d_in[11],
        (float*)d_out);
}

// round 16
// speedup vs baseline: 2.7870x; 2.3745x over previous
#include <cuda_runtime.h>
#include <cuda_fp16.h>

// PLE layers, round 16: gate phase replaced by HMMA gate-GEMM.
//   Evidence: gate dot-product LDGs (nL=32 lines/warp-load) consumed ~half of
//   L1tex capacity (~180us constant across all rounds). G is [n][k] = exactly
//   the W-chunk B layout, so gates are now one extra zero-padded "expert" bank
//   run through the same ldmatrix+mma path (f32 accum for gate precision).
//   Phase 2 = R15 verbatim (f16-accum, group-of-4, 8-slot bulk ring).

#define BT      16384
#define IN_D    256
#define EXP_D   128
#define NE      8
#define TB      64
#define NTH     512
#define XS2     132         // half2 X stride (uints)
#define GSS     57
#define NBUF    8
#define NGRP    48          // groups of 4 chunks (192 expert chunks)
#define CH_U    2048        // uints per chunk: 128 n-rows x 16 kp (8 KB)

// smem word offsets
#define OFF_XS   0                            // 64*132 = 8448 w
#define OFF_WS   8448                         // ring: 8 x 2048 w
#define OFF_WSM  (OFF_WS + NBUF*CH_U)         // 24832
#define OFF_BSM  (OFF_WSM + TB*GSS)           // 28480
#define OFF_MB   (OFF_BSM + 3*1024)           // 31552 (16 mbarriers)
#define SMEM_WORDS (OFF_MB + 32)              // 31584 w = 126,336 B

#define BSWZ(o) ((o) ^ (((o) >> 3) & 0x30))

__device__ __align__(128) unsigned Wc2[NGRP * 4 * CH_U];   // expert chunks
__device__ __align__(128) unsigned Gc2[24 * CH_U];         // gate chunks (3 stacks x 8)

__device__ __forceinline__ void bulk_cp(unsigned dst, const void* src, unsigned bytes,
                                        unsigned mbar) {
    asm volatile(
        "cp.async.bulk.shared::cta.global.mbarrier::complete_tx::bytes [%0], [%1], %2, [%3];"
        :: "r"(dst), "l"(src), "r"(bytes), "r"(mbar) : "memory");
}
#define MBAR_INIT(addr, cnt) \
    asm volatile("mbarrier.init.shared.b64 [%0], %1;" :: "r"(addr), "r"(cnt) : "memory")
#define MBAR_EXPECT_TX(addr, bytes) \
    asm volatile("mbarrier.arrive.expect_tx.shared.b64 _, [%0], %1;" \
                 :: "r"(addr), "r"((unsigned)(bytes)) : "memory")

__device__ __forceinline__ void mbar_wait(unsigned addr, unsigned parity) {
    unsigned done;
    asm volatile("{\n .reg .pred p;\n"
                 " mbarrier.try_wait.parity.acquire.cta.shared::cta.b64 p, [%1], %2;\n"
                 " selp.b32 %0, 1, 0, p;\n}"
                 : "=r"(done) : "r"(addr), "r"(parity) : "memory");
    if (!done) {
        asm volatile("{\n .reg .pred P1;\n"
                     "WL_%=:\n"
                     " mbarrier.try_wait.parity.acquire.cta.shared::cta.b64 P1, [%0], %1, 0x989680;\n"
                     " @P1 bra.uni WD_%=;\n"
                     " bra.uni WL_%=;\n"
                     "WD_%=:\n}"
                     :: "r"(addr), "r"(parity) : "memory");
    }
}

#define LDSM4(r0, r1, r2, r3, addr) \
    asm volatile("ldmatrix.sync.aligned.m8n8.x4.shared.b16 {%0,%1,%2,%3}, [%4];" \
                 : "=r"(r0), "=r"(r1), "=r"(r2), "=r"(r3) : "r"(addr))

// f32-accum HMMA (gate GEMM)
__device__ __forceinline__ void mma16(float& c0, float& c1, float& c2, float& c3,
                                      unsigned a0, unsigned a1, unsigned a2, unsigned a3,
                                      unsigned b0, unsigned b1) {
    asm volatile(
        "mma.sync.aligned.m16n8k16.row.col.f32.f16.f16.f32 "
        "{%0,%1,%2,%3}, {%4,%5,%6,%7}, {%8,%9}, {%0,%1,%2,%3};\n"
        : "+f"(c0), "+f"(c1), "+f"(c2), "+f"(c3)
        : "r"(a0), "r"(a1), "r"(a2), "r"(a3), "r"(b0), "r"(b1));
}
// f16-accum HMMA (expert GEMM)
__device__ __forceinline__ void mma16h(unsigned& d0, unsigned& d1,
                                       unsigned a0, unsigned a1, unsigned a2, unsigned a3,
                                       unsigned b0, unsigned b1) {
    asm volatile(
        "mma.sync.aligned.m16n8k16.row.col.f16.f16.f16.f16 "
        "{%0,%1}, {%2,%3,%4,%5}, {%6,%7}, {%0,%1};\n"
        : "+r"(d0), "+r"(d1)
        : "r"(a0), "r"(a1), "r"(a2), "r"(a3), "r"(b0), "r"(b1));
}

// ---- prepass: W[e][k][n] -> fp16x2 k-pairs, chunk images with baked swizzle ----
__global__ void w_convert2(const float* __restrict__ Wa, const float* __restrict__ Wb,
                           const float* __restrict__ Wsx) {
    int id = blockIdx.x * blockDim.x + threadIdx.x;
    int kp = id & 15;
    int n  = (id >> 4) & 127;
    int c  = (id >> 11) & 7;
    int e  = (id >> 14) & 7;
    int sg = id >> 17;
    const float* W = (sg == 0) ? Wa : (sg == 1) ? Wb : Wsx;
    int k = c * 32 + 2 * kp;
    const float* p = W + ((size_t)e * IN_D + k) * EXP_D + n;
    __half2 h = __floats2half2_rn(p[0], p[EXP_D]);
    unsigned o = (unsigned)(n * 64 + kp * 4);
    int chunk = (sg * 8 + e) * 8 + c;
    *(unsigned*)((char*)(Wc2 + (size_t)chunk * CH_U) + BSWZ(o)) = *(unsigned*)&h;
}

// ---- prepass: G[n][k] -> gate chunk images (rows >= NG zero-padded) ----
__global__ void g_convert(const float* __restrict__ Ga, const float* __restrict__ Gb,
                          const float* __restrict__ Gq) {
    int id = blockIdx.x * blockDim.x + threadIdx.x;   // 24*2048 = 49152
    int kp = id & 15;
    int n  = (id >> 4) & 127;
    int c  = (id >> 11) & 7;
    int sg = id >> 14;
    const float* G = (sg == 0) ? Ga : (sg == 1) ? Gb : Gq;
    const int NG = (sg == 2) ? 24 : 16;
    __half2 h;
    if (n < NG) {
        const float* p = G + (size_t)n * IN_D + c * 32 + 2 * kp;
        h = __floats2half2_rn(p[0], p[1]);            // G is [n][k]: pair contiguous
    } else {
        h = __floats2half2_rn(0.f, 0.f);
    }
    unsigned o = (unsigned)(n * 64 + kp * 4);
    int chunk = sg * 8 + c;
    *(unsigned*)((char*)(Gc2 + (size_t)chunk * CH_U) + BSWZ(o)) = *(unsigned*)&h;
}

// ---------------- main fused kernel ----------------
__global__ __launch_bounds__(NTH, 1)
void ple_kernel(const float* __restrict__ xa, const float* __restrict__ xb,
                const float* __restrict__ xsh,
                const float* __restrict__ ba, const float* __restrict__ bb,
                const float* __restrict__ bsx,
                float* __restrict__ out)
{
    extern __shared__ float smem[];
    unsigned* xs2 = (unsigned*)(smem + OFF_XS);
    float*    wsm = smem + OFF_WSM;
    float*    bsm = smem + OFF_BSM;

    const int tid  = threadIdx.x;
    const int lane = tid & 31;
    const int wid  = tid >> 5;
    const int gid  = lane >> 2;
    const int tig  = lane & 3;
    const int wm   = wid >> 2;                // 0..3 (16-row band)
    const int wn   = wid & 3;                 // 0..3 (32-col band)
    const int sub  = lane >> 3;
    const int l7   = lane & 7;
    const int row0 = blockIdx.x * TB;

    const unsigned xs2_u = (unsigned)__cvta_generic_to_shared(xs2);
    const unsigned ws_u  = (unsigned)__cvta_generic_to_shared(smem + OFF_WS);
    const unsigned mbA   = (unsigned)__cvta_generic_to_shared(smem + OFF_MB);        // phase-2 ring
    const unsigned mbB   = mbA + 64;                                                  // phase-1 gates

    // ldmatrix lane base addresses
    unsigned addrA, addrB[2][2];
    {
        int rowA = wm * 16 + (sub & 1) * 8 + l7;
        addrA = xs2_u + (rowA * XS2 + (sub >> 1) * 4) * 4;
    }
    #pragma unroll
    for (int ntp = 0; ntp < 2; ++ntp) {
        int rowB = wn * 32 + ntp * 16 + (sub >> 1) * 8 + l7;
        unsigned o0 = (unsigned)(rowB * 64 + (sub & 1) * 16);
        unsigned s0 = BSWZ(o0);
        addrB[ntp][0] = ws_u + s0;
        addrB[ntp][1] = ws_u + (s0 ^ 32);
    }

    auto issue_group = [&](int G) {           // phase-2: 4 expert chunks into half G&1
        #pragma unroll
        for (int i = 0; i < 4; ++i) {
            int Q = G * 4 + i;
            int s = ((G & 1) << 2) + i;
            MBAR_EXPECT_TX(mbA + s * 8, CH_U * 4);
            bulk_cp(ws_u + s * CH_U * 4, Wc2 + (size_t)Q * CH_U, CH_U * 4, mbA + s * 8);
        }
    };

    auto stage_x = [&](const float* X) {      // X -> half2 smem tile
        const float4* src = (const float4*)(X + (size_t)row0 * IN_D);
        #pragma unroll
        for (int j = 0; j < 8; ++j) {
            int idx = tid + j * NTH;
            int r = idx >> 6, k4 = idx & 63;
            float4 v = __ldg(src + idx);
            __half2 h0 = __floats2half2_rn(v.x, v.y);
            __half2 h1 = __floats2half2_rn(v.z, v.w);
            uint2 u = { *(unsigned*)&h0, *(unsigned*)&h1 };
            *(uint2*)(xs2 + r * XS2 + 2 * k4) = u;
        }
    };

    if (tid == 0) {
        #pragma unroll
        for (int s = 0; s < 16; ++s) MBAR_INIT(mbA + s * 8, 1);
    }
    __syncthreads();

    for (int i = tid; i < 1024; i += NTH) {
        bsm[i]        = __ldg(ba + i);
        bsm[1024 + i] = __ldg(bb + i);
        bsm[2048 + i] = __ldg(bsx + i);
    }

    // ---------------- Phase 1: gate logits via HMMA + softmax ----------------
    #pragma unroll 1
    for (int sg = 0; sg < 3; ++sg) {
        __syncthreads();                       // prior xs2/ring readers done
        stage_x((sg == 0) ? xa : (sg == 1) ? xb : xsh);
        if (tid == 0) {                        // 8 gate chunks -> ring slots 0..7
            #pragma unroll
            for (int c = 0; c < 8; ++c) {
                MBAR_EXPECT_TX(mbB + c * 8, CH_U * 4);
                bulk_cp(ws_u + c * CH_U * 4, Gc2 + (size_t)(sg * 8 + c) * CH_U,
                        CH_U * 4, mbB + c * 8);
            }
        }
        __syncthreads();                       // X tile visible

        const int NG = (sg == 2) ? 24 : 16, WOFF = sg * 16;
        if (wn == 0) {                         // 4 warps compute all logits (f32 accum)
            float ge[4][4];
            #pragma unroll
            for (int nt = 0; nt < 4; ++nt)
                #pragma unroll
                for (int v = 0; v < 4; ++v) ge[nt][v] = 0.f;
            #pragma unroll 1
            for (int c = 0; c < 8; ++c) {
                mbar_wait(mbB + c * 8, sg & 1);
                const unsigned sb = (unsigned)c * (CH_U * 4);
                unsigned fa0[4], fa1[4], fb[8];
                unsigned ka = (unsigned)(c * 64);
                LDSM4(fa0[0], fa0[1], fa0[2], fa0[3], addrA + ka);
                LDSM4(fa1[0], fa1[1], fa1[2], fa1[3], addrA + ka + 32);
                LDSM4(fb[0], fb[1], fb[2], fb[3], addrB[0][0] + sb);
                LDSM4(fb[4], fb[5], fb[6], fb[7], addrB[1][0] + sb);
                #pragma unroll
                for (int nt = 0; nt < 4; ++nt) {
                    unsigned b0 = fb[(nt >> 1) * 4 + (nt & 1) * 2];
                    unsigned b1 = fb[(nt >> 1) * 4 + (nt & 1) * 2 + 1];
                    mma16(ge[nt][0], ge[nt][1], ge[nt][2], ge[nt][3],
                          fa0[0], fa0[1], fa0[2], fa0[3], b0, b1);
                }
                LDSM4(fb[0], fb[1], fb[2], fb[3], addrB[0][1] + sb);
                LDSM4(fb[4], fb[5], fb[6], fb[7], addrB[1][1] + sb);
                #pragma unroll
                for (int nt = 0; nt < 4; ++nt) {
                    unsigned b0 = fb[(nt >> 1) * 4 + (nt & 1) * 2];
                    unsigned b1 = fb[(nt >> 1) * 4 + (nt & 1) * 2 + 1];
                    mma16(ge[nt][0], ge[nt][1], ge[nt][2], ge[nt][3],
                          fa1[0], fa1[1], fa1[2], fa1[3], b0, b1);
                }
            }
            // scatter logits (cols n < NG) into wsm
            int r0 = wm * 16 + gid;
            #pragma unroll
            for (int nt = 0; nt < 4; ++nt) {
                int n0 = nt * 8 + 2 * tig;
                if (n0 < NG) {
                    wsm[r0 * GSS + WOFF + n0]       = ge[nt][0];
                    wsm[(r0 + 8) * GSS + WOFF + n0] = ge[nt][2];
                }
                if (n0 + 1 < NG) {
                    wsm[r0 * GSS + WOFF + n0 + 1]       = ge[nt][1];
                    wsm[(r0 + 8) * GSS + WOFF + n0 + 1] = ge[nt][3];
                }
            }
        }
        __syncthreads();
        if (sg == 2 && tid == 0) { issue_group(0); issue_group(1); }  // overlap w/ softmax
        if (tid < TB) {
            float* wr = wsm + tid * GSS + WOFF;
            const int NGl = NG;
            float m = wr[0];
            for (int g = 1; g < NGl; ++g) m = fmaxf(m, wr[g]);
            float s = 0.f;
            for (int g = 0; g < NGl; ++g) { float e = expf(wr[g] - m); wr[g] = e; s += e; }
            float inv = 1.f / s;
            for (int g = 0; g < NGl; ++g) wr[g] *= inv;
        }
    }

    // ---------------- Phase 2: fp16-accum expert GEMMs, group-of-4 pipeline ----------
    float oa[4][4] = {}, ob[4][4] = {}, os[4][4] = {};
    float ec[4][4];

    #pragma unroll 1
    for (int g = 0; g < NGRP; ++g) {
        __syncthreads();
        if (tid == 0 && g >= 1 && g + 1 < NGRP) issue_group(g + 1);

        if ((g & 15) == 0) {                   // stack boundary: restage X
            const int sgk = g >> 4;
            stage_x((sgk == 0) ? xa : (sgk == 1) ? xb : xsh);
            __syncthreads();
        }

        #pragma unroll
        for (int i = 0; i < 4; ++i) {
            const int Q = g * 4 + i;
            const int c = Q & 7;
            const int slot = ((g & 1) << 2) + i;
            mbar_wait(mbA + slot * 8, (g >> 1) & 1);

            if (c == 0) {
                #pragma unroll
                for (int nt = 0; nt < 4; ++nt)
                    #pragma unroll
                    for (int v = 0; v < 4; ++v) ec[nt][v] = 0.f;
            }

            const unsigned sb = (unsigned)slot * (CH_U * 4);
            unsigned fa[2][4], fb[8];
            unsigned hc[4][2];
            #pragma unroll
            for (int nt = 0; nt < 4; ++nt) { hc[nt][0] = 0u; hc[nt][1] = 0u; }

            {
                unsigned ka = (unsigned)(c * 64);
                LDSM4(fa[0][0], fa[0][1], fa[0][2], fa[0][3], addrA + ka);
                LDSM4(fa[1][0], fa[1][1], fa[1][2], fa[1][3], addrA + ka + 32);
                LDSM4(fb[0], fb[1], fb[2], fb[3], addrB[0][0] + sb);
                LDSM4(fb[4], fb[5], fb[6], fb[7], addrB[1][0] + sb);
            }
            #pragma unroll
            for (int nt = 0; nt < 4; ++nt) {
                unsigned b0 = fb[(nt >> 1) * 4 + (nt & 1) * 2];
                unsigned b1 = fb[(nt >> 1) * 4 + (nt & 1) * 2 + 1];
                mma16h(hc[nt][0], hc[nt][1],
                       fa[0][0], fa[0][1], fa[0][2], fa[0][3], b0, b1);
            }
            {
                LDSM4(fb[0], fb[1], fb[2], fb[3], addrB[0][1] + sb);
                LDSM4(fb[4], fb[5], fb[6], fb[7], addrB[1][1] + sb);
            }
            #pragma unroll
            for (int nt = 0; nt < 4; ++nt) {
                unsigned b0 = fb[(nt >> 1) * 4 + (nt & 1) * 2];
                unsigned b1 = fb[(nt >> 1) * 4 + (nt & 1) * 2 + 1];
                mma16h(hc[nt][0], hc[nt][1],
                       fa[1][0], fa[1][1], fa[1][2], fa[1][3], b0, b1);
            }
            #pragma unroll
            for (int nt = 0; nt < 4; ++nt) {   // promote K=32 fp16 partial
                __half2 hlo, hhi;
                *(unsigned*)&hlo = hc[nt][0];
                *(unsigned*)&hhi = hc[nt][1];
                float2 lo = __half22float2(hlo);
                float2 hi = __half22float2(hhi);
                ec[nt][0] += lo.x; ec[nt][1] += lo.y;
                ec[nt][2] += hi.x; ec[nt][3] += hi.y;
            }

            if (c == 7) {
                const int e = (Q >> 3) & 7;
                const int sgk = Q >> 6;
                int rl = wm * 16 + gid;
                float w1l, w1h, w2l, w2h, w3l = 0.f, w3h = 0.f;
                if (sgk == 0) {
                    w1l = wsm[rl * GSS + e];      w1h = wsm[(rl + 8) * GSS + e];
                    w2l = wsm[rl * GSS + 32 + e]; w2h = wsm[(rl + 8) * GSS + 32 + e];
                } else if (sgk == 1) {
                    w1l = wsm[rl * GSS + 16 + e]; w1h = wsm[(rl + 8) * GSS + 16 + e];
                    w2l = wsm[rl * GSS + 40 + e]; w2h = wsm[(rl + 8) * GSS + 40 + e];
                } else {
                    w1l = wsm[rl * GSS + 8 + e];  w1h = wsm[(rl + 8) * GSS + 8 + e];
                    w2l = wsm[rl * GSS + 24 + e]; w2h = wsm[(rl + 8) * GSS + 24 + e];
                    w3l = wsm[rl * GSS + 48 + e]; w3h = wsm[(rl + 8) * GSS + 48 + e];
                }
                #pragma unroll
                for (int nt = 0; nt < 4; ++nt) {
                    int c0 = wn * 32 + nt * 8 + 2 * tig;
                    const float* bp = bsm + sgk * 1024 + e * EXP_D + c0;
                    float t0 = ec[nt][0] + bp[0];
                    float t1 = ec[nt][1] + bp[1];
                    float t2 = ec[nt][2] + bp[0];
                    float t3 = ec[nt][3] + bp[1];
                    if (sgk == 0) {
                        oa[nt][0] += w1l * t0; oa[nt][1] += w1l * t1;
                        oa[nt][2] += w1h * t2; oa[nt][3] += w1h * t3;
                        os[nt][0] += w2l * t0; os[nt][1] += w2l * t1;
                        os[nt][2] += w2h * t2; os[nt][3] += w2h * t3;
                    } else if (sgk == 1) {
                        ob[nt][0] += w1l * t0; ob[nt][1] += w1l * t1;
                        ob[nt][2] += w1h * t2; ob[nt][3] += w1h * t3;
                        os[nt][0] += w2l * t0; os[nt][1] += w2l * t1;
                        os[nt][2] += w2h * t2; os[nt][3] += w2h * t3;
                    } else {
                        oa[nt][0] += w1l * t0; oa[nt][1] += w1l * t1;
                        oa[nt][2] += w1h * t2; oa[nt][3] += w1h * t3;
                        ob[nt][0] += w2l * t0; ob[nt][1] += w2l * t1;
                        ob[nt][2] += w2h * t2; ob[nt][3] += w2h * t3;
                        os[nt][0] += w3l * t0; os[nt][1] += w3l * t1;
                        os[nt][2] += w3h * t2; os[nt][3] += w3h * t3;
                    }
                }
            }
        }
    }

    // ---------------- write out: [out_a | out_b | out_s], each [B,128] ----------------
    const size_t OS = (size_t)BT * EXP_D;
    {
        int r = row0 + wm * 16 + gid;
        #pragma unroll
        for (int nt = 0; nt < 4; ++nt) {
            int c0 = wn * 32 + nt * 8 + 2 * tig;
            size_t p0 = (size_t)r * EXP_D + c0;
            size_t p1 = (size_t)(r + 8) * EXP_D + c0;
            *(float2*)(out + p0)          = make_float2(oa[nt][0], oa[nt][1]);
            *(float2*)(out + p1)          = make_float2(oa[nt][2], oa[nt][3]);
            *(float2*)(out + OS + p0)     = make_float2(ob[nt][0], ob[nt][1]);
            *(float2*)(out + OS + p1)     = make_float2(ob[nt][2], ob[nt][3]);
            *(float2*)(out + 2 * OS + p0) = make_float2(os[nt][0], os[nt][1]);
            *(float2*)(out + 2 * OS + p1) = make_float2(os[nt][2], os[nt][3]);
        }
    }
}

extern "C" void kernel_launch(void* const* d_in, const int* in_sizes, int n_in,
                              void* d_out, int out_size) {
    (void)in_sizes; (void)n_in; (void)out_size;

    w_convert2<<<1536, 256>>>((const float*)d_in[3], (const float*)d_in[5],
                              (const float*)d_in[7]);
    g_convert<<<192, 256>>>((const float*)d_in[9], (const float*)d_in[10],
                            (const float*)d_in[11]);

    constexpr int SMEM_BYTES = SMEM_WORDS * 4;   // 126,336 B
    cudaFuncSetAttribute(ple_kernel, cudaFuncAttributeMaxDynamicSharedMemorySize, SMEM_BYTES);
    ple_kernel<<<BT / TB, NTH, SMEM_BYTES>>>(
        (const float*)d_in[0], (const float*)d_in[1], (const float*)d_in[2],
        (const float*)d_in[4], (const float*)d_in[6], (const float*)d_in[8],
        (float*)d_out);
}